// round 1
// baseline (speedup 1.0000x reference)
#include <cuda_runtime.h>
#include <math.h>

#define NCELLS   (512 * 512)     // grid cells per batch
#define M_LEN    262144          // k-space points per batch
#define NCOILS   16
#define NJ       6
#define CENTER   3072            // floor(J*L/2)
#define TBL_LEN  6145            // J*L + 1
#define NBATCH   2

// Transposed grid: xT[b][cell][coil][ri], 2*262144*32 floats = 67MB static scratch
__device__ float g_xT[(size_t)NBATCH * NCELLS * NCOILS * 2];

// ---------------------------------------------------------------------------
// Transpose x[b][c][ri][cell] -> xT[b][cell][c*2+ri]
// One thread per (b, cell): 32 coalesced strided reads, contiguous 128B write.
// ---------------------------------------------------------------------------
__global__ void transpose_kernel(const float* __restrict__ x) {
    int idx  = blockIdx.x * blockDim.x + threadIdx.x;   // 0 .. 2*NCELLS-1
    int b    = idx >> 18;                               // / 262144
    int cell = idx & (NCELLS - 1);

    float v[32];
#pragma unroll
    for (int c = 0; c < NCOILS; c++) {
        v[c * 2 + 0] = x[((size_t)((b * NCOILS + c) * 2 + 0)) * NCELLS + cell];
        v[c * 2 + 1] = x[((size_t)((b * NCOILS + c) * 2 + 1)) * NCELLS + cell];
    }
    float4* dst = reinterpret_cast<float4*>(g_xT + ((size_t)(b * NCELLS + cell)) * 32);
#pragma unroll
    for (int i = 0; i < 8; i++) dst[i] = reinterpret_cast<float4*>(v)[i];
}

// ---------------------------------------------------------------------------
// Main interpolation kernel.
// Block = 256 threads = 16 points x 16 coils.  p = tid>>4 (point slot),
// c = tid&15 (coil).  Per-point setup (table lookups, offsets, phase) done by
// the c==0 lane into smem; gather loop loads float2 per (cell, coil) from the
// transposed grid (16 lanes -> one 128B line).  Output staged via smem for
// m-contiguous stores.
// ---------------------------------------------------------------------------
__global__ __launch_bounds__(256) void interp_kernel(
    const float* __restrict__ om,
    const float* __restrict__ t0,
    const float* __restrict__ t1,
    float* __restrict__ out)
{
    __shared__ int   s_row[16][NJ];
    __shared__ int   s_col[16][NJ];
    __shared__ float s_c0r[16][NJ], s_c0i[16][NJ];
    __shared__ float s_c1r[16][NJ], s_c1i[16][NJ];
    __shared__ float s_pr[16], s_pi[16];
    __shared__ float s_out[32 * 17];   // rows = (coil,ri), 16 p + 1 pad

    const int tid = threadIdx.x;
    const int p   = tid >> 4;
    const int c   = tid & 15;

    const int b_blk = (blockIdx.x * 16) >> 18;            // batch (uniform per block)
    const int m0    = (blockIdx.x * 16) & (M_LEN - 1);    // first m of block
    const int m     = m0 + p;

    if (c == 0) {
        const float om0 = om[(size_t)(b_blk * 2 + 0) * M_LEN + m];
        const float om1 = om[(size_t)(b_blk * 2 + 1) * M_LEN + m];
        const float SCALE = 512.0f / (2.0f * 3.14159265358979323846f);
        const float tm0 = om0 * SCALE;
        const float tm1 = om1 * SCALE;
        const float k0 = 1.0f + floorf(tm0 - 3.0f);
        const float k1 = 1.0f + floorf(tm1 - 3.0f);
        const int gi0 = (int)k0;
        const int gi1 = (int)k1;
#pragma unroll
        for (int j = 0; j < NJ; j++) {
            int d0 = __float2int_rn((tm0 - (k0 + (float)j)) * 1024.0f) + CENTER;
            int d1 = __float2int_rn((tm1 - (k1 + (float)j)) * 1024.0f) + CENTER;
            s_c0r[p][j] = t0[d0];
            s_c0i[p][j] = t0[TBL_LEN + d0];
            s_c1r[p][j] = t1[d1];
            s_c1i[p][j] = t1[TBL_LEN + d1];
            s_row[p][j] = ((gi0 + j) & 511) << 9;   // row * 512
            s_col[p][j] = (gi1 + j) & 511;
        }
        float ph = om0 * 128.0f + om1 * 128.0f;
        float sp, cp;
        sincosf(ph, &sp, &cp);
        s_pr[p] = cp;
        s_pi[p] = sp;
    }
    __syncthreads();

    // base pointer: this batch's transposed grid, this coil's float2 slot
    const float2* xb = reinterpret_cast<const float2*>(
                           g_xT + ((size_t)b_blk * NCELLS) * 32) + c;

    float ar = 0.0f, ai = 0.0f;
#pragma unroll
    for (int j0 = 0; j0 < NJ; j0++) {
        const int   row = s_row[p][j0];
        const float c0r = s_c0r[p][j0];
        const float c0i = s_c0i[p][j0];
#pragma unroll
        for (int j1 = 0; j1 < NJ; j1++) {
            const int cell = row + s_col[p][j1];
            const float c1r = s_c1r[p][j1];
            const float c1i = s_c1i[p][j1];
            const float cr = c0r * c1r - c0i * c1i;
            const float ci = c0r * c1i + c0i * c1r;
            const float2 d = __ldg(&xb[(size_t)cell * 16]);
            ar += cr * d.x - ci * d.y;
            ai += cr * d.y + ci * d.x;
        }
    }

    const float pr = s_pr[p];
    const float pi = s_pi[p];
    const float yr = ar * pr - ai * pi;
    const float yi = ar * pi + ai * pr;

    s_out[(c * 2 + 0) * 17 + p] = yr;
    s_out[(c * 2 + 1) * 17 + p] = yi;
    __syncthreads();

    // Write out[b][c2][ri][m0+pp], m-contiguous runs of 16 per (c2,ri)
#pragma unroll
    for (int i = tid; i < 512; i += 256) {
        const int pp = i & 15;
        const int ri = (i >> 4) & 1;
        const int c2 = i >> 5;
        out[((size_t)(b_blk * NCOILS + c2) * 2 + ri) * M_LEN + m0 + pp] =
            s_out[(c2 * 2 + ri) * 17 + pp];
    }
}

extern "C" void kernel_launch(void* const* d_in, const int* in_sizes, int n_in,
                              void* d_out, int out_size) {
    const float* x  = (const float*)d_in[0];   // (2,16,2,512,512)
    const float* om = (const float*)d_in[1];   // (2,2,262144)
    const float* t0 = (const float*)d_in[2];   // (2,6145)
    const float* t1 = (const float*)d_in[3];   // (2,6145)
    float* out = (float*)d_out;                // (2,16,2,262144)

    transpose_kernel<<<(NBATCH * NCELLS) / 256, 256>>>(x);
    interp_kernel<<<(NBATCH * M_LEN) / 16, 256>>>(om, t0, t1, out);
}

// round 2
// speedup vs baseline: 1.2911x; 1.2911x over previous
#include <cuda_runtime.h>
#include <math.h>

#define NCELLS   (512 * 512)     // grid cells per batch
#define M_LEN    262144          // k-space points per batch
#define NCOILS   16
#define NJ       6
#define CENTER   3072            // floor(J*L/2)
#define TBL_LEN  6145            // J*L + 1
#define NBATCH   2
#define PTS      32              // points per block

// Transposed grid: xT[b][cell][coil][ri], 128B per cell line
__device__ float g_xT[(size_t)NBATCH * NCELLS * NCOILS * 2];

// ---------------------------------------------------------------------------
// Transpose x[b][c][ri][cell] -> xT[b][cell][c*2+ri]
// ---------------------------------------------------------------------------
__global__ void transpose_kernel(const float* __restrict__ x) {
    int idx  = blockIdx.x * blockDim.x + threadIdx.x;   // 0 .. 2*NCELLS-1
    int b    = idx >> 18;
    int cell = idx & (NCELLS - 1);

    float v[32];
#pragma unroll
    for (int c = 0; c < NCOILS; c++) {
        v[c * 2 + 0] = __ldg(&x[((size_t)((b * NCOILS + c) * 2 + 0)) * NCELLS + cell]);
        v[c * 2 + 1] = __ldg(&x[((size_t)((b * NCOILS + c) * 2 + 1)) * NCELLS + cell]);
    }
    float4* dst = reinterpret_cast<float4*>(g_xT + ((size_t)(b * NCELLS + cell)) * 32);
#pragma unroll
    for (int i = 0; i < 8; i++) dst[i] = reinterpret_cast<float4*>(v)[i];
}

// ---------------------------------------------------------------------------
// Interp: block = 256 thr = 32 points x 8 coil-pair lanes.
// Setup lane (c4==0) precomputes 36 {coef_r, coef_i, byte_offset} per point.
// Main loop: per 2-coil neighbor = LDS.128 + LDG.128 + 8 FFMA.
// ---------------------------------------------------------------------------
__global__ __launch_bounds__(256, 4) void interp_kernel(
    const float* __restrict__ om,
    const float* __restrict__ t0,
    const float* __restrict__ t1,
    float* __restrict__ out)
{
    __shared__ float4 s_cf[PTS][36];        // {cr, ci, byteoff_as_float, 0}
    __shared__ float  s_pr[PTS], s_pi[PTS];
    __shared__ float  s_out[32 * 33];       // rows=(coil,ri), 32 p + 1 pad

    const int tid = threadIdx.x;
    const int p   = tid >> 3;               // point slot 0..31
    const int c4  = tid & 7;                // coil-pair lane 0..7

    const int gbase = blockIdx.x * PTS;
    const int b_blk = gbase >> 18;                 // batch (uniform per block)
    const int m0    = gbase & (M_LEN - 1);
    const int m     = m0 + p;

    if (c4 == 0) {
        const float om0 = om[(size_t)(b_blk * 2 + 0) * M_LEN + m];
        const float om1 = om[(size_t)(b_blk * 2 + 1) * M_LEN + m];
        const float SCALE = 512.0f / (2.0f * 3.14159265358979323846f);
        const float tm0 = om0 * SCALE;
        const float tm1 = om1 * SCALE;
        const float k0 = 1.0f + floorf(tm0 - 3.0f);
        const float k1 = 1.0f + floorf(tm1 - 3.0f);
        const int gi0 = (int)k0;
        const int gi1 = (int)k1;

        float c0r[NJ], c0i[NJ], c1r[NJ], c1i[NJ];
        int   row[NJ], col[NJ];
#pragma unroll
        for (int j = 0; j < NJ; j++) {
            int d0 = __float2int_rn((tm0 - (k0 + (float)j)) * 1024.0f) + CENTER;
            int d1 = __float2int_rn((tm1 - (k1 + (float)j)) * 1024.0f) + CENTER;
            c0r[j] = __ldg(&t0[d0]);
            c0i[j] = __ldg(&t0[TBL_LEN + d0]);
            c1r[j] = __ldg(&t1[d1]);
            c1i[j] = __ldg(&t1[TBL_LEN + d1]);
            row[j] = ((gi0 + j) & 511) << 9;
            col[j] = (gi1 + j) & 511;
        }
#pragma unroll
        for (int j0 = 0; j0 < NJ; j0++) {
#pragma unroll
            for (int j1 = 0; j1 < NJ; j1++) {
                float cr = c0r[j0] * c1r[j1] - c0i[j0] * c1i[j1];
                float ci = c0r[j0] * c1i[j1] + c0i[j0] * c1r[j1];
                int off = (row[j0] + col[j1]) << 7;   // cell * 128 bytes
                s_cf[p][j0 * NJ + j1] =
                    make_float4(cr, ci, __int_as_float(off), 0.0f);
            }
        }
        float ph = om0 * 128.0f + om1 * 128.0f;
        float sp, cp;
        sincosf(ph, &sp, &cp);
        s_pr[p] = cp;
        s_pi[p] = sp;
    }
    __syncthreads();

    // base: this batch's grid, this lane's 16B slot within each 128B cell line
    const char* xb = reinterpret_cast<const char*>(
                         g_xT + ((size_t)b_blk * NCELLS) * 32) + c4 * 16;

    float ar0 = 0.f, ai0 = 0.f, ar1 = 0.f, ai1 = 0.f;
#pragma unroll
    for (int g = 0; g < 6; g++) {
        float4 cf[6], d[6];
#pragma unroll
        for (int k = 0; k < 6; k++) cf[k] = s_cf[p][g * 6 + k];
#pragma unroll
        for (int k = 0; k < 6; k++)
            d[k] = __ldg(reinterpret_cast<const float4*>(
                       xb + (size_t)(unsigned)__float_as_int(cf[k].z)));
#pragma unroll
        for (int k = 0; k < 6; k++) {
            ar0 += cf[k].x * d[k].x - cf[k].y * d[k].y;
            ai0 += cf[k].x * d[k].y + cf[k].y * d[k].x;
            ar1 += cf[k].x * d[k].z - cf[k].y * d[k].w;
            ai1 += cf[k].x * d[k].w + cf[k].y * d[k].z;
        }
    }

    const float pr = s_pr[p];
    const float pi = s_pi[p];
    // coil 2*c4
    s_out[(c4 * 4 + 0) * 33 + p] = ar0 * pr - ai0 * pi;
    s_out[(c4 * 4 + 1) * 33 + p] = ar0 * pi + ai0 * pr;
    // coil 2*c4+1
    s_out[(c4 * 4 + 2) * 33 + p] = ar1 * pr - ai1 * pi;
    s_out[(c4 * 4 + 3) * 33 + p] = ar1 * pi + ai1 * pr;
    __syncthreads();

    // out[b][c2][ri][m0 + pp] — m-contiguous runs of 32 (128B) per (c2,ri)
#pragma unroll
    for (int i = tid; i < 1024; i += 256) {
        const int pp = i & 31;
        const int r  = i >> 5;          // r = c2*2 + ri
        out[((size_t)(b_blk * NCOILS * 2) + r) * M_LEN + m0 + pp] =
            s_out[r * 33 + pp];
    }
}

extern "C" void kernel_launch(void* const* d_in, const int* in_sizes, int n_in,
                              void* d_out, int out_size) {
    const float* x  = (const float*)d_in[0];   // (2,16,2,512,512)
    const float* om = (const float*)d_in[1];   // (2,2,262144)
    const float* t0 = (const float*)d_in[2];   // (2,6145)
    const float* t1 = (const float*)d_in[3];   // (2,6145)
    float* out = (float*)d_out;                // (2,16,2,262144)

    transpose_kernel<<<(NBATCH * NCELLS) / 256, 256>>>(x);
    interp_kernel<<<(NBATCH * M_LEN) / PTS, 256>>>(om, t0, t1, out);
}

// round 3
// speedup vs baseline: 1.3880x; 1.0751x over previous
#include <cuda_runtime.h>
#include <cuda_fp16.h>
#include <math.h>

#define NCELLS   (512 * 512)     // grid cells per batch
#define M_LEN    262144          // k-space points per batch
#define NCOILS   16
#define NJ       6
#define CENTER   3072            // floor(J*L/2)
#define TBL_LEN  6145            // J*L + 1
#define NBATCH   2
#define WPB      8               // warps (=points) per block

// Transposed fp16 grid: xT[b][cell][coil] as half2(re,im); 64B per cell
__device__ __half2 g_xT[(size_t)NBATCH * NCELLS * NCOILS];

// ---------------------------------------------------------------------------
// Transpose + fp16 convert: x[b][c][ri][cell] -> g_xT[b*NCELLS+cell][c]
// ---------------------------------------------------------------------------
__global__ void transpose_kernel(const float* __restrict__ x) {
    int idx  = blockIdx.x * blockDim.x + threadIdx.x;   // 0 .. 2*NCELLS-1
    int b    = idx >> 18;
    int cell = idx & (NCELLS - 1);

    const float* xb = x + (size_t)b * NCOILS * 2 * NCELLS + cell;
    __half2 v[NCOILS];
#pragma unroll
    for (int c = 0; c < NCOILS; c++) {
        float re = __ldg(xb + (size_t)(c * 2 + 0) * NCELLS);
        float im = __ldg(xb + (size_t)(c * 2 + 1) * NCELLS);
        v[c] = __floats2half2_rn(re, im);
    }
    uint4* dst = reinterpret_cast<uint4*>(g_xT + (size_t)idx * NCOILS);
#pragma unroll
    for (int i = 0; i < 4; i++) dst[i] = reinterpret_cast<uint4*>(v)[i];
}

// ---------------------------------------------------------------------------
// Interp: 256 threads = 8 warps; one point per warp.
// Lane l: cc = l&15 (coil), ks = l>>4 (which cell of each adjacent pair).
// Each LDG.32 warp-instruction covers 2 adjacent j1-cells x 16 coils = 128B.
// ---------------------------------------------------------------------------
__global__ __launch_bounds__(256) void interp_kernel(
    const float* __restrict__ om,
    const float* __restrict__ t0,
    const float* __restrict__ t1,
    float* __restrict__ out)
{
    __shared__ float2 s_c0[WPB][NJ];     // (c0r, c0i) per j0
    __shared__ float2 s_c1[WPB][NJ];     // (c1r, c1i) per j1
    __shared__ float2 s_cf[WPB][36];     // complex coef products
    __shared__ float2 s_ph[WPB];         // phase (cos, sin)
    __shared__ float  s_out[32][9];      // rows=(coil,ri), 8 pts + pad

    const int tid  = threadIdx.x;
    const int w    = tid >> 5;
    const int lane = tid & 31;
    const unsigned FULL = 0xffffffffu;

    const int gbase = blockIdx.x * WPB;
    const int b_blk = gbase >> 18;                 // batch (uniform per block)
    const int m0    = gbase & (M_LEN - 1);
    const int m     = m0 + w;

    // ---- per-point setup, parallel across the warp ----
    const float om0 = __ldg(&om[(size_t)(b_blk * 2 + 0) * M_LEN + m]);
    const float om1 = __ldg(&om[(size_t)(b_blk * 2 + 1) * M_LEN + m]);
    const float SCALE = 512.0f / (2.0f * 3.14159265358979323846f);
    const float tm0 = om0 * SCALE;
    const float tm1 = om1 * SCALE;
    const float k0f = 1.0f + floorf(tm0 - 3.0f);
    const float k1f = 1.0f + floorf(tm1 - 3.0f);
    const int gi0 = (int)k0f;
    const int gi1 = (int)k1f;

    if (lane < NJ) {
        int j = lane;
        int d0 = __float2int_rn((tm0 - (k0f + (float)j)) * 1024.0f) + CENTER;
        s_c0[w][j] = make_float2(__ldg(&t0[d0]), __ldg(&t0[TBL_LEN + d0]));
    } else if (lane >= 8 && lane < 8 + NJ) {
        int j = lane - 8;
        int d1 = __float2int_rn((tm1 - (k1f + (float)j)) * 1024.0f) + CENTER;
        s_c1[w][j] = make_float2(__ldg(&t1[d1]), __ldg(&t1[TBL_LEN + d1]));
    } else if (lane == 16) {
        float ph = om0 * 128.0f + om1 * 128.0f;
        float sp, cp;
        sincosf(ph, &sp, &cp);
        s_ph[w] = make_float2(cp, sp);
    }
    __syncwarp(FULL);

#pragma unroll
    for (int i = lane; i < 36; i += 32) {
        int j0 = i / 6, j1 = i - j0 * 6;
        float2 a = s_c0[w][j0];
        float2 bb = s_c1[w][j1];
        s_cf[w][i] = make_float2(a.x * bb.x - a.y * bb.y,
                                 a.x * bb.y + a.y * bb.x);
    }
    __syncwarp(FULL);

    // ---- gather loop ----
    const int cc = lane & 15;
    const int ks = lane >> 4;
    const char* xb = reinterpret_cast<const char*>(
                         g_xT + (size_t)b_blk * NCELLS * NCOILS) + cc * 4;

    float ar = 0.0f, ai = 0.0f;
#pragma unroll
    for (int j0 = 0; j0 < NJ; j0++) {
        const char* rp = xb + (((gi0 + j0) & 511) << 15);   // row*512*64B
        const float2* cfrow = &s_cf[w][j0 * 6];
#pragma unroll
        for (int kp = 0; kp < 3; kp++) {
            const int j1 = kp * 2 + ks;
            const int colb = ((gi1 + j1) & 511) << 6;       // col*64B
            const float2 cf = cfrow[j1];
            const __half2 h = *reinterpret_cast<const __half2*>(rp + colb);
            const float2 d = __half22float2(h);
            ar = fmaf(cf.x, d.x, ar);
            ar = fmaf(-cf.y, d.y, ar);
            ai = fmaf(cf.x, d.y, ai);
            ai = fmaf(cf.y, d.x, ai);
        }
    }

    // combine the two cell-halves (same coil, ks=0/1)
    ar += __shfl_xor_sync(FULL, ar, 16);
    ai += __shfl_xor_sync(FULL, ai, 16);

    if (lane < 16) {
        const float2 ph = s_ph[w];
        s_out[cc * 2 + 0][w] = ar * ph.x - ai * ph.y;
        s_out[cc * 2 + 1][w] = ar * ph.y + ai * ph.x;
    }
    __syncthreads();

    // out[b][c][ri][m0+pp]: 32 rows x 8 consecutive m (32B runs)
    {
        const int r  = tid >> 3;
        const int pp = tid & 7;
        out[((size_t)(b_blk * NCOILS * 2) + r) * M_LEN + m0 + pp] = s_out[r][pp];
    }
}

extern "C" void kernel_launch(void* const* d_in, const int* in_sizes, int n_in,
                              void* d_out, int out_size) {
    const float* x  = (const float*)d_in[0];   // (2,16,2,512,512)
    const float* om = (const float*)d_in[1];   // (2,2,262144)
    const float* t0 = (const float*)d_in[2];   // (2,6145)
    const float* t1 = (const float*)d_in[3];   // (2,6145)
    float* out = (float*)d_out;                // (2,16,2,262144)

    transpose_kernel<<<(NBATCH * NCELLS) / 256, 256>>>(x);
    interp_kernel<<<(NBATCH * M_LEN) / WPB, 256>>>(om, t0, t1, out);
}

// round 4
// speedup vs baseline: 1.8140x; 1.3069x over previous
#include <cuda_runtime.h>
#include <cuda_fp16.h>
#include <math.h>

#define NCELLS   (512 * 512)
#define M_LEN    262144
#define NCOILS   16
#define NJ       6
#define CENTER   3072
#define TBL_LEN  6145
#define NBATCH   2
#define WPB      8               // warps (=points) per block

#define HROWS    517             // 512 + 5 halo
#define HSTRIDE  520             // padded row stride in cells (128B-aligned rows)

// Halo-padded transposed fp16 grid: [b][r<517][c<520][coil] half2; 64B/cell
__device__ __half2 g_xT[(size_t)NBATCH * HROWS * HSTRIDE * NCOILS];

// ---------------------------------------------------------------------------
// Transpose + fp16 + halo: x[b][coil][ri][cell] -> g_xT[b][r][c][coil]
// ---------------------------------------------------------------------------
__global__ void transpose_kernel(const float* __restrict__ x) {
    int idx = blockIdx.x * blockDim.x + threadIdx.x;
    if (idx >= NBATCH * HROWS * HROWS) return;
    int b   = idx / (HROWS * HROWS);
    int rem = idx - b * (HROWS * HROWS);
    int r   = rem / HROWS;
    int c   = rem - r * HROWS;
    int cell = ((r & 511) << 9) | (c & 511);

    const float* xb = x + (size_t)b * NCOILS * 2 * NCELLS + cell;
    __half2 v[NCOILS];
#pragma unroll
    for (int cc = 0; cc < NCOILS; cc++) {
        float re = __ldg(xb + (size_t)(cc * 2 + 0) * NCELLS);
        float im = __ldg(xb + (size_t)(cc * 2 + 1) * NCELLS);
        v[cc] = __floats2half2_rn(re, im);
    }
    uint4* dst = reinterpret_cast<uint4*>(
        g_xT + ((size_t)(b * HROWS + r) * HSTRIDE + c) * NCOILS);
#pragma unroll
    for (int i = 0; i < 4; i++) dst[i] = reinterpret_cast<uint4*>(v)[i];
}

// ---------------------------------------------------------------------------
// Interp: 256 thr = 8 warps, one point/warp. Lane = (ks = l>>4, cc = l&15).
// Row sums in half2 HFMA2 with register-resident c1 coefs (selected by ks);
// c0 applied per row in fp32. All neighbor offsets are immediates (halo).
// ---------------------------------------------------------------------------
__global__ __launch_bounds__(256) void interp_kernel(
    const float* __restrict__ om,
    const float* __restrict__ t0,
    const float* __restrict__ t1,
    float* __restrict__ out)
{
    __shared__ float2 s_c0[WPB][NJ];      // fp32 (c0r, c0i)
    __shared__ uint2  s_c1[WPB][NJ];      // packed {h2(c1r,c1r), h2(-c1i,c1i)}
    __shared__ float2 s_ph[WPB];
    __shared__ float  s_out[32][9];

    const int tid  = threadIdx.x;
    const int w    = tid >> 5;
    const int lane = tid & 31;
    const unsigned FULL = 0xffffffffu;

    const int gbase = blockIdx.x * WPB;
    const int b_blk = gbase >> 18;
    const int m0    = gbase & (M_LEN - 1);
    const int m     = m0 + w;

    const float om0 = __ldg(&om[(size_t)(b_blk * 2 + 0) * M_LEN + m]);
    const float om1 = __ldg(&om[(size_t)(b_blk * 2 + 1) * M_LEN + m]);
    const float SCALE = 512.0f / (2.0f * 3.14159265358979323846f);
    const float tm0 = om0 * SCALE;
    const float tm1 = om1 * SCALE;
    const float k0f = 1.0f + floorf(tm0 - 3.0f);
    const float k1f = 1.0f + floorf(tm1 - 3.0f);
    const int gi0 = (int)k0f;
    const int gi1 = (int)k1f;

    if (lane < NJ) {
        int j = lane;
        int d0 = __float2int_rn((tm0 - (k0f + (float)j)) * 1024.0f) + CENTER;
        s_c0[w][j] = make_float2(__ldg(&t0[d0]), __ldg(&t0[TBL_LEN + d0]));
    } else if (lane >= 8 && lane < 8 + NJ) {
        int j = lane - 8;
        int d1 = __float2int_rn((tm1 - (k1f + (float)j)) * 1024.0f) + CENTER;
        float c1r = __ldg(&t1[d1]);
        float c1i = __ldg(&t1[TBL_LEN + d1]);
        __half2 A = __floats2half2_rn(c1r, c1r);
        __half2 B = __floats2half2_rn(-c1i, c1i);
        s_c1[w][j] = make_uint2(*(unsigned*)&A, *(unsigned*)&B);
    } else if (lane == 16) {
        float ph = om0 * 128.0f + om1 * 128.0f;
        float sp, cp;
        sincosf(ph, &sp, &cp);
        s_ph[w] = make_float2(cp, sp);
    }
    __syncwarp(FULL);

    const int cc = lane & 15;
    const int ks = lane >> 4;

    // register-resident c1 coefs for this lane's j1 set {ks, 2+ks, 4+ks}
    uint2 p0 = s_c1[w][ks];
    uint2 p1 = s_c1[w][2 + ks];
    uint2 p2 = s_c1[w][4 + ks];
    const __half2 A0 = *(__half2*)&p0.x, B0 = *(__half2*)&p0.y;
    const __half2 A1 = *(__half2*)&p1.x, B1 = *(__half2*)&p1.y;
    const __half2 A2 = *(__half2*)&p2.x, B2 = *(__half2*)&p2.y;
    float2 c0[NJ];
#pragma unroll
    for (int j = 0; j < NJ; j++) c0[j] = s_c0[w][j];

    const int row0 = gi0 & 511;
    const int col0 = gi1 & 511;
    const __half2* base = g_xT
        + ((size_t)(b_blk * HROWS + row0) * HSTRIDE + col0) * NCOILS
        + ks * NCOILS + cc;

    float ar = 0.0f, ai = 0.0f;
#pragma unroll
    for (int j0 = 0; j0 < NJ; j0++) {
        const __half2* rp = base + j0 * (HSTRIDE * NCOILS);  // immediate
        const __half2 d0 = __ldg(rp);
        const __half2 d1 = __ldg(rp + 2 * NCOILS);
        const __half2 d2 = __ldg(rp + 4 * NCOILS);
        __half2 racc;
        racc = __hmul2(A0, d0);
        racc = __hfma2(B0, __lowhigh2highlow(d0), racc);
        racc = __hfma2(A1, d1, racc);
        racc = __hfma2(B1, __lowhigh2highlow(d1), racc);
        racc = __hfma2(A2, d2, racc);
        racc = __hfma2(B2, __lowhigh2highlow(d2), racc);
        const float2 rf = __half22float2(racc);
        ar = fmaf(c0[j0].x, rf.x, ar);
        ar = fmaf(-c0[j0].y, rf.y, ar);
        ai = fmaf(c0[j0].x, rf.y, ai);
        ai = fmaf(c0[j0].y, rf.x, ai);
    }

    ar += __shfl_xor_sync(FULL, ar, 16);
    ai += __shfl_xor_sync(FULL, ai, 16);

    if (lane < 16) {
        const float2 ph = s_ph[w];
        s_out[cc * 2 + 0][w] = ar * ph.x - ai * ph.y;
        s_out[cc * 2 + 1][w] = ar * ph.y + ai * ph.x;
    }
    __syncthreads();

    {
        const int r  = tid >> 3;
        const int pp = tid & 7;
        out[((size_t)(b_blk * NCOILS * 2) + r) * M_LEN + m0 + pp] = s_out[r][pp];
    }
}

extern "C" void kernel_launch(void* const* d_in, const int* in_sizes, int n_in,
                              void* d_out, int out_size) {
    const float* x  = (const float*)d_in[0];   // (2,16,2,512,512)
    const float* om = (const float*)d_in[1];   // (2,2,262144)
    const float* t0 = (const float*)d_in[2];   // (2,6145)
    const float* t1 = (const float*)d_in[3];   // (2,6145)
    float* out = (float*)d_out;                // (2,16,2,262144)

    int ncells_h = NBATCH * HROWS * HROWS;
    transpose_kernel<<<(ncells_h + 255) / 256, 256>>>(x);
    interp_kernel<<<(NBATCH * M_LEN) / WPB, 256>>>(om, t0, t1, out);
}

// round 5
// speedup vs baseline: 2.2427x; 1.2363x over previous
#include <cuda_runtime.h>
#include <cuda_fp16.h>
#include <math.h>

#define NCELLS   (512 * 512)
#define M_LEN    262144
#define NCOILS   16
#define NJ       6
#define CENTER   3072
#define TBL_LEN  6145
#define NBATCH   2
#define WPB      8               // warps per block
#define PPB      16              // points per block (2 per warp)

#define HROWS    517             // 512 + 5 halo
#define HSTRIDE  520             // padded row stride in cells

// Halo-padded transposed fp16 grid: [b][r<517][c<520][coil] half2; 64B/cell
__device__ __half2 g_xT[(size_t)NBATCH * HROWS * HSTRIDE * NCOILS];

// ---------------------------------------------------------------------------
// Transpose + fp16 + halo: x[b][coil][ri][cell] -> g_xT[b][r][c][coil]
// ---------------------------------------------------------------------------
__global__ void transpose_kernel(const float* __restrict__ x) {
    int idx = blockIdx.x * blockDim.x + threadIdx.x;
    if (idx >= NBATCH * HROWS * HROWS) return;
    int b   = idx / (HROWS * HROWS);
    int rem = idx - b * (HROWS * HROWS);
    int r   = rem / HROWS;
    int c   = rem - r * HROWS;
    int cell = ((r & 511) << 9) | (c & 511);

    const float* xb = x + (size_t)b * NCOILS * 2 * NCELLS + cell;
    __half2 v[NCOILS];
#pragma unroll
    for (int cc = 0; cc < NCOILS; cc++) {
        float re = __ldg(xb + (size_t)(cc * 2 + 0) * NCELLS);
        float im = __ldg(xb + (size_t)(cc * 2 + 1) * NCELLS);
        v[cc] = __floats2half2_rn(re, im);
    }
    uint4* dst = reinterpret_cast<uint4*>(
        g_xT + ((size_t)(b * HROWS + r) * HSTRIDE + c) * NCOILS);
#pragma unroll
    for (int i = 0; i < 4; i++) dst[i] = reinterpret_cast<uint4*>(v)[i];
}

// ---------------------------------------------------------------------------
// Interp: 256 thr = 8 warps; TWO points per warp (one per half-warp).
// Lane: pt = l>>4, ks = (l>>3)&1 (cell slot), cc4 = l&7 (coil pair).
// Each LDG.64 loads 2 coils; warp-instruction covers 2pts x 2cells x 16coils.
// ---------------------------------------------------------------------------
__global__ __launch_bounds__(256) void interp_kernel(
    const float* __restrict__ om,
    const float* __restrict__ t0,
    const float* __restrict__ t1,
    float* __restrict__ out)
{
    __shared__ float2 s_c0[WPB][2][NJ];    // fp32 (c0r, c0i)
    __shared__ uint2  s_c1[WPB][2][NJ];    // {h2(c1r,c1r), h2(-c1i,c1i)}
    __shared__ float2 s_ph[WPB][2];
    __shared__ float  s_out[32][PPB + 1];

    const int tid  = threadIdx.x;
    const int w    = tid >> 5;
    const int lane = tid & 31;
    const int pt   = lane >> 4;
    const int hl   = lane & 15;
    const unsigned FULL = 0xffffffffu;

    const int gbase = blockIdx.x * PPB;
    const int b_blk = gbase >> 18;
    const int m0    = gbase & (M_LEN - 1);
    const int m     = m0 + w * 2 + pt;

    const float om0 = __ldg(&om[(size_t)(b_blk * 2 + 0) * M_LEN + m]);
    const float om1 = __ldg(&om[(size_t)(b_blk * 2 + 1) * M_LEN + m]);
    const float SCALE = 512.0f / (2.0f * 3.14159265358979323846f);
    const float tm0 = om0 * SCALE;
    const float tm1 = om1 * SCALE;
    const float k0f = 1.0f + floorf(tm0 - 3.0f);
    const float k1f = 1.0f + floorf(tm1 - 3.0f);
    const int gi0 = (int)k0f;
    const int gi1 = (int)k1f;

    if (hl < NJ) {
        int j = hl;
        int d0 = __float2int_rn((tm0 - (k0f + (float)j)) * 1024.0f) + CENTER;
        s_c0[w][pt][j] = make_float2(__ldg(&t0[d0]), __ldg(&t0[TBL_LEN + d0]));
    } else if (hl >= 8 && hl < 8 + NJ) {
        int j = hl - 8;
        int d1 = __float2int_rn((tm1 - (k1f + (float)j)) * 1024.0f) + CENTER;
        float c1r = __ldg(&t1[d1]);
        float c1i = __ldg(&t1[TBL_LEN + d1]);
        __half2 A = __floats2half2_rn(c1r, c1r);
        __half2 B = __floats2half2_rn(-c1i, c1i);
        s_c1[w][pt][j] = make_uint2(*(unsigned*)&A, *(unsigned*)&B);
    } else if (hl == 6) {
        float ph = om0 * 128.0f + om1 * 128.0f;
        float sp, cp;
        sincosf(ph, &sp, &cp);
        s_ph[w][pt] = make_float2(cp, sp);
    }
    __syncwarp(FULL);

    const int cc4 = lane & 7;
    const int ks  = (lane >> 3) & 1;

    // register-resident c1 coefs for this lane's j1 set {ks, 2+ks, 4+ks}
    uint2 p0 = s_c1[w][pt][ks];
    uint2 p1 = s_c1[w][pt][2 + ks];
    uint2 p2 = s_c1[w][pt][4 + ks];
    const __half2 A0 = *(__half2*)&p0.x, B0 = *(__half2*)&p0.y;
    const __half2 A1 = *(__half2*)&p1.x, B1 = *(__half2*)&p1.y;
    const __half2 A2 = *(__half2*)&p2.x, B2 = *(__half2*)&p2.y;
    float2 c0[NJ];
#pragma unroll
    for (int j = 0; j < NJ; j++) c0[j] = s_c0[w][pt][j];

    const int row0 = gi0 & 511;
    const int col0 = gi1 & 511;
    // lane base: batch grid + (row0, col0 + ks) cell + coils {2cc4, 2cc4+1}
    const __half2* base = g_xT
        + ((size_t)(b_blk * HROWS + row0) * HSTRIDE + col0 + ks) * NCOILS
        + cc4 * 2;

    float arA = 0.f, aiA = 0.f, arB = 0.f, aiB = 0.f;
#pragma unroll
    for (int j0 = 0; j0 < NJ; j0++) {
        const __half2* rp = base + j0 * (HSTRIDE * NCOILS);   // immediate
        const uint2 d0 = __ldg(reinterpret_cast<const uint2*>(rp));
        const uint2 d1 = __ldg(reinterpret_cast<const uint2*>(rp + 2 * NCOILS));
        const uint2 d2 = __ldg(reinterpret_cast<const uint2*>(rp + 4 * NCOILS));

        const __half2 a0 = *(const __half2*)&d0.x, b0 = *(const __half2*)&d0.y;
        const __half2 a1 = *(const __half2*)&d1.x, b1 = *(const __half2*)&d1.y;
        const __half2 a2 = *(const __half2*)&d2.x, b2 = *(const __half2*)&d2.y;

        __half2 rA = __hmul2(A0, a0);
        rA = __hfma2(B0, __lowhigh2highlow(a0), rA);
        rA = __hfma2(A1, a1, rA);
        rA = __hfma2(B1, __lowhigh2highlow(a1), rA);
        rA = __hfma2(A2, a2, rA);
        rA = __hfma2(B2, __lowhigh2highlow(a2), rA);

        __half2 rB = __hmul2(A0, b0);
        rB = __hfma2(B0, __lowhigh2highlow(b0), rB);
        rB = __hfma2(A1, b1, rB);
        rB = __hfma2(B1, __lowhigh2highlow(b1), rB);
        rB = __hfma2(A2, b2, rB);
        rB = __hfma2(B2, __lowhigh2highlow(b2), rB);

        const float2 fA = __half22float2(rA);
        const float2 fB = __half22float2(rB);
        const float cr = c0[j0].x, ci = c0[j0].y;
        arA = fmaf(cr, fA.x, arA); arA = fmaf(-ci, fA.y, arA);
        aiA = fmaf(cr, fA.y, aiA); aiA = fmaf(ci, fA.x, aiA);
        arB = fmaf(cr, fB.x, arB); arB = fmaf(-ci, fB.y, arB);
        aiB = fmaf(cr, fB.y, aiB); aiB = fmaf(ci, fB.x, aiB);
    }

    // combine the two cell slots (ks=0/1) within each half-warp
    arA += __shfl_xor_sync(FULL, arA, 8);
    aiA += __shfl_xor_sync(FULL, aiA, 8);
    arB += __shfl_xor_sync(FULL, arB, 8);
    aiB += __shfl_xor_sync(FULL, aiB, 8);

    if (ks == 0) {
        const float2 ph = s_ph[w][pt];
        const int pp = w * 2 + pt;
        s_out[cc4 * 4 + 0][pp] = arA * ph.x - aiA * ph.y;  // coil 2cc4 re
        s_out[cc4 * 4 + 1][pp] = arA * ph.y + aiA * ph.x;  // coil 2cc4 im
        s_out[cc4 * 4 + 2][pp] = arB * ph.x - aiB * ph.y;  // coil 2cc4+1 re
        s_out[cc4 * 4 + 3][pp] = arB * ph.y + aiB * ph.x;  // coil 2cc4+1 im
    }
    __syncthreads();

    // out[b][coil][ri][m0+pp]: 32 rows x 16 consecutive m (64B runs)
#pragma unroll
    for (int i = tid; i < 32 * PPB; i += 256) {
        const int pp = i & (PPB - 1);
        const int r  = i >> 4;
        out[((size_t)(b_blk * NCOILS * 2) + r) * M_LEN + m0 + pp] = s_out[r][pp];
    }
}

extern "C" void kernel_launch(void* const* d_in, const int* in_sizes, int n_in,
                              void* d_out, int out_size) {
    const float* x  = (const float*)d_in[0];   // (2,16,2,512,512)
    const float* om = (const float*)d_in[1];   // (2,2,262144)
    const float* t0 = (const float*)d_in[2];   // (2,6145)
    const float* t1 = (const float*)d_in[3];   // (2,6145)
    float* out = (float*)d_out;                // (2,16,2,262144)

    int ncells_h = NBATCH * HROWS * HROWS;
    transpose_kernel<<<(ncells_h + 255) / 256, 256>>>(x);
    interp_kernel<<<(NBATCH * M_LEN) / PPB, 256>>>(om, t0, t1, out);
}

// round 6
// speedup vs baseline: 2.2809x; 1.0170x over previous
#include <cuda_runtime.h>
#include <cuda_fp16.h>
#include <math.h>

#define NCELLS   (512 * 512)
#define M_LEN    262144
#define NCOILS   16
#define NJ       6
#define CENTER   3072
#define TBL_LEN  6145
#define NBATCH   2
#define WPB      8               // warps per block
#define PPB      32              // points per block (4 per warp)

#define HROWS    517             // 512 + 5 halo
#define HSTRIDE  520             // padded row stride in cells
#define ROW_U4   (HSTRIDE * 4)   // row stride in uint4 units (cell = 4x uint4)

// Halo-padded transposed fp16 grid: [b][r<517][c<520][coil] half2; 64B/cell
__device__ __half2 g_xT[(size_t)NBATCH * HROWS * HSTRIDE * NCOILS];

// ---------------------------------------------------------------------------
// Transpose + fp16 + halo: x[b][coil][ri][cell] -> g_xT[b][r][c][coil]
// ---------------------------------------------------------------------------
__global__ void transpose_kernel(const float* __restrict__ x) {
    int idx = blockIdx.x * blockDim.x + threadIdx.x;
    if (idx >= NBATCH * HROWS * HROWS) return;
    int b   = idx / (HROWS * HROWS);
    int rem = idx - b * (HROWS * HROWS);
    int r   = rem / HROWS;
    int c   = rem - r * HROWS;
    int cell = ((r & 511) << 9) | (c & 511);

    const float* xb = x + (size_t)b * NCOILS * 2 * NCELLS + cell;
    __half2 v[NCOILS];
#pragma unroll
    for (int cc = 0; cc < NCOILS; cc++) {
        float re = __ldg(xb + (size_t)(cc * 2 + 0) * NCELLS);
        float im = __ldg(xb + (size_t)(cc * 2 + 1) * NCELLS);
        v[cc] = __floats2half2_rn(re, im);
    }
    uint4* dst = reinterpret_cast<uint4*>(
        g_xT + ((size_t)(b * HROWS + r) * HSTRIDE + c) * NCOILS);
#pragma unroll
    for (int i = 0; i < 4; i++) dst[i] = reinterpret_cast<uint4*>(v)[i];
}

// ---------------------------------------------------------------------------
// Interp: 256 thr = 8 warps; FOUR points per warp (8 lanes each).
// Lane: pt = l>>3, ks = (l>>2)&1 (cell slot), cc = l&3 (coil quad, LDG.128).
// Swap-free split accumulation: R1,R2 per row (c1), G1..G4 across rows (c0),
// all in HFMA2; single fp32 recombination per point.
// ---------------------------------------------------------------------------
__global__ __launch_bounds__(256, 4) void interp_kernel(
    const float* __restrict__ om,
    const float* __restrict__ t0,
    const float* __restrict__ t1,
    float* __restrict__ out)
{
    __shared__ uint2  s_c0[WPB][4][NJ];   // {h2(c0r,c0r), h2(c0i,c0i)}
    __shared__ uint2  s_c1[WPB][4][NJ];   // {h2(c1r,c1r), h2(c1i,-c1i)}
    __shared__ float2 s_ph[WPB][4];
    __shared__ float  s_out[32][PPB + 1];

    const int tid  = threadIdx.x;
    const int w    = tid >> 5;
    const int lane = tid & 31;
    const int pt   = lane >> 3;           // point within warp
    const int g    = lane & 7;            // lane within point group
    const unsigned FULL = 0xffffffffu;

    const int gbase = blockIdx.x * PPB;
    const int b_blk = gbase >> 18;
    const int m0    = gbase & (M_LEN - 1);
    const int m     = m0 + w * 4 + pt;

    const float om0 = __ldg(&om[(size_t)(b_blk * 2 + 0) * M_LEN + m]);
    const float om1 = __ldg(&om[(size_t)(b_blk * 2 + 1) * M_LEN + m]);
    const float SCALE = 512.0f / (2.0f * 3.14159265358979323846f);
    const float tm0 = om0 * SCALE;
    const float tm1 = om1 * SCALE;
    const float k0f = 1.0f + floorf(tm0 - 3.0f);
    const float k1f = 1.0f + floorf(tm1 - 3.0f);
    const int gi0 = (int)k0f;
    const int gi1 = (int)k1f;

    // setup: lane g handles items {g, g+8}; items 0-5: c0[j], 6-11: c1[j-6],
    // 12: phase
#pragma unroll
    for (int it = 0; it < 2; it++) {
        const int item = g + it * 8;
        if (item < 6) {
            const int j = item;
            int d0 = __float2int_rn((tm0 - (k0f + (float)j)) * 1024.0f) + CENTER;
            float c0r = __ldg(&t0[d0]);
            float c0i = __ldg(&t0[TBL_LEN + d0]);
            __half2 R = __floats2half2_rn(c0r, c0r);
            __half2 I = __floats2half2_rn(c0i, c0i);
            s_c0[w][pt][j] = make_uint2(*(unsigned*)&R, *(unsigned*)&I);
        } else if (item < 12) {
            const int j = item - 6;
            int d1 = __float2int_rn((tm1 - (k1f + (float)j)) * 1024.0f) + CENTER;
            float c1r = __ldg(&t1[d1]);
            float c1i = __ldg(&t1[TBL_LEN + d1]);
            __half2 A  = __floats2half2_rn(c1r, c1r);
            __half2 Bp = __floats2half2_rn(c1i, -c1i);
            s_c1[w][pt][j] = make_uint2(*(unsigned*)&A, *(unsigned*)&Bp);
        } else if (item == 12) {
            float ph = om0 * 128.0f + om1 * 128.0f;
            float sp, cp;
            sincosf(ph, &sp, &cp);
            s_ph[w][pt] = make_float2(cp, sp);
        }
    }
    __syncwarp(FULL);

    const int cc = lane & 3;              // coil quad: coils 4cc..4cc+3
    const int ks = (lane >> 2) & 1;       // cell slot within adjacent pair

    // register c1 coefs for this lane's j1 set {ks, 2+ks, 4+ks}
    const uint2 q0 = s_c1[w][pt][ks];
    const uint2 q1 = s_c1[w][pt][2 + ks];
    const uint2 q2 = s_c1[w][pt][4 + ks];
    const __half2 A0 = *(__half2*)&q0.x, B0 = *(__half2*)&q0.y;
    const __half2 A1 = *(__half2*)&q1.x, B1 = *(__half2*)&q1.y;
    const __half2 A2 = *(__half2*)&q2.x, B2 = *(__half2*)&q2.y;

    const int row0 = gi0 & 511;
    const int col0 = gi1 & 511;
    const uint4* base = reinterpret_cast<const uint4*>(g_xT)
        + ((size_t)(b_blk * HROWS + row0) * HSTRIDE + col0 + ks) * 4 + cc;

    const __half2 hz = __floats2half2_rn(0.f, 0.f);
    __half2 G1[4], G2[4], G3[4], G4[4];
#pragma unroll
    for (int c = 0; c < 4; c++) { G1[c] = hz; G2[c] = hz; G3[c] = hz; G4[c] = hz; }

#pragma unroll
    for (int j0 = 0; j0 < NJ; j0++) {
        const uint4* rp = base + j0 * ROW_U4;
        const uint4 d0 = __ldg(rp);
        const uint4 d1 = __ldg(rp + 8);    // +2 cells
        const uint4 d2 = __ldg(rp + 16);   // +4 cells
        const __half2* e0 = reinterpret_cast<const __half2*>(&d0);
        const __half2* e1 = reinterpret_cast<const __half2*>(&d1);
        const __half2* e2 = reinterpret_cast<const __half2*>(&d2);

        const uint2 c0p = s_c0[w][pt][j0];
        const __half2 C0R = *(const __half2*)&c0p.x;
        const __half2 C0I = *(const __half2*)&c0p.y;

#pragma unroll
        for (int c = 0; c < 4; c++) {
            __half2 r1 = __hmul2(A0, e0[c]);
            r1 = __hfma2(A1, e1[c], r1);
            r1 = __hfma2(A2, e2[c], r1);
            __half2 r2 = __hmul2(B0, e0[c]);
            r2 = __hfma2(B1, e1[c], r2);
            r2 = __hfma2(B2, e2[c], r2);
            G1[c] = __hfma2(C0R, r1, G1[c]);
            G2[c] = __hfma2(C0R, r2, G2[c]);
            G3[c] = __hfma2(C0I, r1, G3[c]);
            G4[c] = __hfma2(C0I, r2, G4[c]);
        }
    }

    // reduce the two cell slots (ks pair = lane xor 4), in half2
#pragma unroll
    for (int c = 0; c < 4; c++) {
        unsigned u;
        u = __shfl_xor_sync(FULL, *(unsigned*)&G1[c], 4);
        G1[c] = __hadd2(G1[c], *(__half2*)&u);
        u = __shfl_xor_sync(FULL, *(unsigned*)&G2[c], 4);
        G2[c] = __hadd2(G2[c], *(__half2*)&u);
        u = __shfl_xor_sync(FULL, *(unsigned*)&G3[c], 4);
        G3[c] = __hadd2(G3[c], *(__half2*)&u);
        u = __shfl_xor_sync(FULL, *(unsigned*)&G4[c], 4);
        G4[c] = __hadd2(G4[c], *(__half2*)&u);
    }

    if (ks == 0) {
        const float2 ph = s_ph[w][pt];
        const int pp = w * 4 + pt;
#pragma unroll
        for (int c = 0; c < 4; c++) {
            const float2 g1 = __half22float2(G1[c]);
            const float2 g2 = __half22float2(G2[c]);
            const float2 g3 = __half22float2(G3[c]);
            const float2 g4 = __half22float2(G4[c]);
            const float ar = g1.x + g2.y - g3.y - g4.x;
            const float ai = g1.y + g2.x + g3.x + g4.y;
            const int coil = cc * 4 + c;
            s_out[coil * 2 + 0][pp] = ar * ph.x - ai * ph.y;
            s_out[coil * 2 + 1][pp] = ar * ph.y + ai * ph.x;
        }
    }
    __syncthreads();

    // out[b][coil][ri][m0+pp]: 32 rows x 32 consecutive m (128B runs)
#pragma unroll
    for (int i = tid; i < 32 * PPB; i += 256) {
        const int pp = i & (PPB - 1);
        const int r  = i >> 5;
        out[((size_t)(b_blk * NCOILS * 2) + r) * M_LEN + m0 + pp] = s_out[r][pp];
    }
}

extern "C" void kernel_launch(void* const* d_in, const int* in_sizes, int n_in,
                              void* d_out, int out_size) {
    const float* x  = (const float*)d_in[0];   // (2,16,2,512,512)
    const float* om = (const float*)d_in[1];   // (2,2,262144)
    const float* t0 = (const float*)d_in[2];   // (2,6145)
    const float* t1 = (const float*)d_in[3];   // (2,6145)
    float* out = (float*)d_out;                // (2,16,2,262144)

    int ncells_h = NBATCH * HROWS * HROWS;
    transpose_kernel<<<(ncells_h + 255) / 256, 256>>>(x);
    interp_kernel<<<(NBATCH * M_LEN) / PPB, 256>>>(om, t0, t1, out);
}

// round 7
// speedup vs baseline: 2.3526x; 1.0315x over previous
#include <cuda_runtime.h>
#include <cuda_fp16.h>
#include <math.h>

#define NCELLS   (512 * 512)
#define M_LEN    262144
#define NCOILS   16
#define NJ       6
#define CENTER   3072
#define TBL_LEN  6145
#define NBATCH   2
#define WPB      8               // warps per block
#define PPB      32              // points per block (4 per warp)

#define HROWS    517             // 512 + 5 halo
#define HSTRIDE  520             // padded row stride in cells
#define ROW_U4   (HSTRIDE * 4)   // row stride in uint4 units

// Halo-padded transposed fp16 grid: [b][r<517][c<520][coil] half2; 64B/cell
__device__ __half2 g_xT[(size_t)NBATCH * HROWS * HSTRIDE * NCOILS];

// ---------------------------------------------------------------------------
// Transpose + fp16 + halo, 2 cells per thread (float2 reads when no wrap).
// ---------------------------------------------------------------------------
#define CPAIRS 259   // ceil(517/2)
__global__ void transpose_kernel(const float* __restrict__ x) {
    int idx = blockIdx.x * blockDim.x + threadIdx.x;
    if (idx >= NBATCH * HROWS * CPAIRS) return;
    int b   = idx / (HROWS * CPAIRS);
    int rem = idx - b * (HROWS * CPAIRS);
    int r   = rem / CPAIRS;
    int c2  = rem - r * CPAIRS;
    int c   = c2 * 2;
    const int row = (r & 511) << 9;
    const int col0 = c & 511;
    const bool has2 = (c + 1) < HROWS;
    const bool vec  = has2 && (col0 < 511);

    const float* xb = x + (size_t)b * NCOILS * 2 * NCELLS + row;
    __half2 v0[NCOILS], v1[NCOILS];
    if (vec) {
#pragma unroll
        for (int cc = 0; cc < NCOILS; cc++) {
            float2 re = __ldg(reinterpret_cast<const float2*>(
                            xb + (size_t)(cc * 2 + 0) * NCELLS + col0));
            float2 im = __ldg(reinterpret_cast<const float2*>(
                            xb + (size_t)(cc * 2 + 1) * NCELLS + col0));
            v0[cc] = __floats2half2_rn(re.x, im.x);
            v1[cc] = __floats2half2_rn(re.y, im.y);
        }
    } else {
        const int cA = col0;
        const int cB = (c + 1) & 511;
#pragma unroll
        for (int cc = 0; cc < NCOILS; cc++) {
            float reA = __ldg(xb + (size_t)(cc * 2 + 0) * NCELLS + cA);
            float imA = __ldg(xb + (size_t)(cc * 2 + 1) * NCELLS + cA);
            v0[cc] = __floats2half2_rn(reA, imA);
            float reB = __ldg(xb + (size_t)(cc * 2 + 0) * NCELLS + cB);
            float imB = __ldg(xb + (size_t)(cc * 2 + 1) * NCELLS + cB);
            v1[cc] = __floats2half2_rn(reB, imB);
        }
    }
    uint4* dst = reinterpret_cast<uint4*>(
        g_xT + ((size_t)(b * HROWS + r) * HSTRIDE + c) * NCOILS);
#pragma unroll
    for (int i = 0; i < 4; i++) dst[i] = reinterpret_cast<uint4*>(v0)[i];
    if (has2) {
#pragma unroll
        for (int i = 0; i < 4; i++) dst[4 + i] = reinterpret_cast<uint4*>(v1)[i];
    }
}

// ---------------------------------------------------------------------------
// Interp: 256 thr = 8 warps; 4 points per warp (8 lanes each).
// Lane: pt = l>>3, ks = (l>>2)&1, cc = l&3 (coil quad via LDG.128).
// S-trick: S = r1 + swap(r2); G1 += c0r*S, G2 += c0i*S (2 chains per coil);
// ar = G1.x - G2.y, ai = G1.y + G2.x after ks-reduction.
// ---------------------------------------------------------------------------
__global__ __launch_bounds__(256, 5) void interp_kernel(
    const float* __restrict__ om,
    const float* __restrict__ t0,
    const float* __restrict__ t1,
    float* __restrict__ out)
{
    __shared__ uint2  s_c0[WPB][4][NJ];   // {h2(c0r,c0r), h2(c0i,c0i)}
    __shared__ uint2  s_c1[WPB][4][NJ];   // {h2(c1r,c1r), h2(c1i,-c1i)}
    __shared__ float2 s_ph[WPB][4];
    __shared__ float  s_out[32][PPB + 1];

    const int tid  = threadIdx.x;
    const int w    = tid >> 5;
    const int lane = tid & 31;
    const int pt   = lane >> 3;
    const int g    = lane & 7;
    const unsigned FULL = 0xffffffffu;

    const int gbase = blockIdx.x * PPB;
    const int b_blk = gbase >> 18;
    const int m0    = gbase & (M_LEN - 1);
    const int m     = m0 + w * 4 + pt;

    const float om0 = __ldg(&om[(size_t)(b_blk * 2 + 0) * M_LEN + m]);
    const float om1 = __ldg(&om[(size_t)(b_blk * 2 + 1) * M_LEN + m]);
    const float SCALE = 512.0f / (2.0f * 3.14159265358979323846f);
    const float tm0 = om0 * SCALE;
    const float tm1 = om1 * SCALE;
    const float k0f = 1.0f + floorf(tm0 - 3.0f);
    const float k1f = 1.0f + floorf(tm1 - 3.0f);
    const int gi0 = (int)k0f;
    const int gi1 = (int)k1f;

#pragma unroll
    for (int it = 0; it < 2; it++) {
        const int item = g + it * 8;
        if (item < 6) {
            const int j = item;
            int d0 = __float2int_rn((tm0 - (k0f + (float)j)) * 1024.0f) + CENTER;
            float c0r = __ldg(&t0[d0]);
            float c0i = __ldg(&t0[TBL_LEN + d0]);
            __half2 R = __floats2half2_rn(c0r, c0r);
            __half2 I = __floats2half2_rn(c0i, c0i);
            s_c0[w][pt][j] = make_uint2(*(unsigned*)&R, *(unsigned*)&I);
        } else if (item < 12) {
            const int j = item - 6;
            int d1 = __float2int_rn((tm1 - (k1f + (float)j)) * 1024.0f) + CENTER;
            float c1r = __ldg(&t1[d1]);
            float c1i = __ldg(&t1[TBL_LEN + d1]);
            __half2 A  = __floats2half2_rn(c1r, c1r);
            __half2 Bp = __floats2half2_rn(c1i, -c1i);
            s_c1[w][pt][j] = make_uint2(*(unsigned*)&A, *(unsigned*)&Bp);
        } else if (item == 12) {
            float ph = om0 * 128.0f + om1 * 128.0f;
            float sp, cp;
            sincosf(ph, &sp, &cp);
            s_ph[w][pt] = make_float2(cp, sp);
        }
    }
    __syncwarp(FULL);

    const int cc = lane & 3;
    const int ks = (lane >> 2) & 1;

    const uint2 q0 = s_c1[w][pt][ks];
    const uint2 q1 = s_c1[w][pt][2 + ks];
    const uint2 q2 = s_c1[w][pt][4 + ks];
    const __half2 A0 = *(__half2*)&q0.x, B0 = *(__half2*)&q0.y;
    const __half2 A1 = *(__half2*)&q1.x, B1 = *(__half2*)&q1.y;
    const __half2 A2 = *(__half2*)&q2.x, B2 = *(__half2*)&q2.y;

    const int row0 = gi0 & 511;
    const int col0 = gi1 & 511;
    const uint4* base = reinterpret_cast<const uint4*>(g_xT)
        + ((size_t)(b_blk * HROWS + row0) * HSTRIDE + col0 + ks) * 4 + cc;

    const __half2 hz = __floats2half2_rn(0.f, 0.f);
    __half2 G1[4], G2[4];
#pragma unroll
    for (int c = 0; c < 4; c++) { G1[c] = hz; G2[c] = hz; }

#pragma unroll
    for (int j0 = 0; j0 < NJ; j0++) {
        const uint4* rp = base + j0 * ROW_U4;
        const uint4 d0 = __ldg(rp);
        const uint4 d1 = __ldg(rp + 8);    // +2 cells
        const uint4 d2 = __ldg(rp + 16);   // +4 cells
        const __half2* e0 = reinterpret_cast<const __half2*>(&d0);
        const __half2* e1 = reinterpret_cast<const __half2*>(&d1);
        const __half2* e2 = reinterpret_cast<const __half2*>(&d2);

        const uint2 c0p = s_c0[w][pt][j0];
        const __half2 C0R = *(const __half2*)&c0p.x;
        const __half2 C0I = *(const __half2*)&c0p.y;

#pragma unroll
        for (int c = 0; c < 4; c++) {
            __half2 r1 = __hmul2(A0, e0[c]);
            r1 = __hfma2(A1, e1[c], r1);
            r1 = __hfma2(A2, e2[c], r1);
            __half2 r2 = __hmul2(B0, e0[c]);
            r2 = __hfma2(B1, e1[c], r2);
            r2 = __hfma2(B2, e2[c], r2);
            const __half2 S = __hadd2(r1, __lowhigh2highlow(r2));
            G1[c] = __hfma2(C0R, S, G1[c]);
            G2[c] = __hfma2(C0I, S, G2[c]);
        }
    }

    // reduce the two cell slots (lane xor 4) in half2
#pragma unroll
    for (int c = 0; c < 4; c++) {
        unsigned u;
        u = __shfl_xor_sync(FULL, *(unsigned*)&G1[c], 4);
        G1[c] = __hadd2(G1[c], *(__half2*)&u);
        u = __shfl_xor_sync(FULL, *(unsigned*)&G2[c], 4);
        G2[c] = __hadd2(G2[c], *(__half2*)&u);
    }

    if (ks == 0) {
        const float2 ph = s_ph[w][pt];
        const int pp = w * 4 + pt;
#pragma unroll
        for (int c = 0; c < 4; c++) {
            const float2 g1 = __half22float2(G1[c]);
            const float2 g2 = __half22float2(G2[c]);
            const float ar = g1.x - g2.y;
            const float ai = g1.y + g2.x;
            const int coil = cc * 4 + c;
            s_out[coil * 2 + 0][pp] = ar * ph.x - ai * ph.y;
            s_out[coil * 2 + 1][pp] = ar * ph.y + ai * ph.x;
        }
    }
    __syncthreads();

    // out[b][coil][ri][m0+pp]: 32 rows x 32 consecutive m (128B runs)
#pragma unroll
    for (int i = tid; i < 32 * PPB; i += 256) {
        const int pp = i & (PPB - 1);
        const int r  = i >> 5;
        out[((size_t)(b_blk * NCOILS * 2) + r) * M_LEN + m0 + pp] = s_out[r][pp];
    }
}

extern "C" void kernel_launch(void* const* d_in, const int* in_sizes, int n_in,
                              void* d_out, int out_size) {
    const float* x  = (const float*)d_in[0];   // (2,16,2,512,512)
    const float* om = (const float*)d_in[1];   // (2,2,262144)
    const float* t0 = (const float*)d_in[2];   // (2,6145)
    const float* t1 = (const float*)d_in[3];   // (2,6145)
    float* out = (float*)d_out;                // (2,16,2,262144)

    int npairs = NBATCH * HROWS * CPAIRS;
    transpose_kernel<<<(npairs + 255) / 256, 256>>>(x);
    interp_kernel<<<(NBATCH * M_LEN) / PPB, 256>>>(om, t0, t1, out);
}

// round 8
// speedup vs baseline: 2.4807x; 1.0545x over previous
#include <cuda_runtime.h>
#include <cuda_fp16.h>
#include <math.h>

#define NCELLS   (512 * 512)
#define M_LEN    262144
#define NCOILS   16
#define NJ       6
#define CENTER   3072
#define TBL_LEN  6145
#define NBATCH   2
#define WPB      8               // warps per block
#define PPB      32              // points per block (4 per warp)

#define HROWS    517             // 512 + 5 halo
#define HSTRIDE  520             // padded row stride in cells (even!)
#define ROW_U4   (HSTRIDE * 4)   // row stride in uint4 units

// Two alignment copies of the halo-padded fp16 grid (64B per cell):
//   copy A: cell c at slot c        (even col0 points read here)
//   copy B: cell c at slot c + 1    (odd  col0 points read here)
// => the 6-cell row window always starts at a 128B-aligned slot.
__device__ __align__(256) __half2 g_xTa[(size_t)NBATCH * HROWS * HSTRIDE * NCOILS];
__device__ __align__(256) __half2 g_xTb[(size_t)NBATCH * HROWS * HSTRIDE * NCOILS];

// ---------------------------------------------------------------------------
// Transpose + fp16 + halo: x[b][coil][ri][cell] -> both alignment copies
// ---------------------------------------------------------------------------
__global__ void transpose_kernel(const float* __restrict__ x) {
    int idx = blockIdx.x * blockDim.x + threadIdx.x;
    if (idx >= NBATCH * HROWS * HROWS) return;
    int b   = idx / (HROWS * HROWS);
    int rem = idx - b * (HROWS * HROWS);
    int r   = rem / HROWS;
    int c   = rem - r * HROWS;
    int cell = ((r & 511) << 9) | (c & 511);

    const float* xb = x + (size_t)b * NCOILS * 2 * NCELLS + cell;
    __half2 v[NCOILS];
#pragma unroll
    for (int cc = 0; cc < NCOILS; cc++) {
        float re = __ldg(xb + (size_t)(cc * 2 + 0) * NCELLS);
        float im = __ldg(xb + (size_t)(cc * 2 + 1) * NCELLS);
        v[cc] = __floats2half2_rn(re, im);
    }
    const size_t slot = ((size_t)(b * HROWS + r) * HSTRIDE + c) * NCOILS;
    uint4* dstA = reinterpret_cast<uint4*>(g_xTa + slot);
    uint4* dstB = reinterpret_cast<uint4*>(g_xTb + slot + NCOILS);  // c -> c+1
#pragma unroll
    for (int i = 0; i < 4; i++) dstA[i] = reinterpret_cast<uint4*>(v)[i];
#pragma unroll
    for (int i = 0; i < 4; i++) dstB[i] = reinterpret_cast<uint4*>(v)[i];
}

// ---------------------------------------------------------------------------
// Interp: 256 thr = 8 warps; 4 points per warp (8 lanes each).
// Lane: pt = l>>3, ks = (l>>2)&1, cc = l&3 (coil quad via LDG.128).
// Parity-selected grid copy makes every 128B slice line-aligned.
// S-trick: S = r1 + swap(r2); G1 += c0r*S, G2 += c0i*S;
// ar = G1.x - G2.y, ai = G1.y + G2.x after ks-reduction.
// ---------------------------------------------------------------------------
__global__ __launch_bounds__(256, 5) void interp_kernel(
    const float* __restrict__ om,
    const float* __restrict__ t0,
    const float* __restrict__ t1,
    float* __restrict__ out)
{
    __shared__ uint2  s_c0[WPB][4][NJ];   // {h2(c0r,c0r), h2(c0i,c0i)}
    __shared__ uint2  s_c1[WPB][4][NJ];   // {h2(c1r,c1r), h2(c1i,-c1i)}
    __shared__ float2 s_ph[WPB][4];
    __shared__ float  s_out[32][PPB + 1];

    const int tid  = threadIdx.x;
    const int w    = tid >> 5;
    const int lane = tid & 31;
    const int pt   = lane >> 3;
    const int g    = lane & 7;
    const unsigned FULL = 0xffffffffu;

    const int gbase = blockIdx.x * PPB;
    const int b_blk = gbase >> 18;
    const int m0    = gbase & (M_LEN - 1);
    const int m     = m0 + w * 4 + pt;

    const float om0 = __ldg(&om[(size_t)(b_blk * 2 + 0) * M_LEN + m]);
    const float om1 = __ldg(&om[(size_t)(b_blk * 2 + 1) * M_LEN + m]);
    const float SCALE = 512.0f / (2.0f * 3.14159265358979323846f);
    const float tm0 = om0 * SCALE;
    const float tm1 = om1 * SCALE;
    const float k0f = 1.0f + floorf(tm0 - 3.0f);
    const float k1f = 1.0f + floorf(tm1 - 3.0f);
    const int gi0 = (int)k0f;
    const int gi1 = (int)k1f;

#pragma unroll
    for (int it = 0; it < 2; it++) {
        const int item = g + it * 8;
        if (item < 6) {
            const int j = item;
            int d0 = __float2int_rn((tm0 - (k0f + (float)j)) * 1024.0f) + CENTER;
            float c0r = __ldg(&t0[d0]);
            float c0i = __ldg(&t0[TBL_LEN + d0]);
            __half2 R = __floats2half2_rn(c0r, c0r);
            __half2 I = __floats2half2_rn(c0i, c0i);
            s_c0[w][pt][j] = make_uint2(*(unsigned*)&R, *(unsigned*)&I);
        } else if (item < 12) {
            const int j = item - 6;
            int d1 = __float2int_rn((tm1 - (k1f + (float)j)) * 1024.0f) + CENTER;
            float c1r = __ldg(&t1[d1]);
            float c1i = __ldg(&t1[TBL_LEN + d1]);
            __half2 A  = __floats2half2_rn(c1r, c1r);
            __half2 Bp = __floats2half2_rn(c1i, -c1i);
            s_c1[w][pt][j] = make_uint2(*(unsigned*)&A, *(unsigned*)&Bp);
        } else if (item == 12) {
            float ph = om0 * 128.0f + om1 * 128.0f;
            float sp, cp;
            sincosf(ph, &sp, &cp);
            s_ph[w][pt] = make_float2(cp, sp);
        }
    }
    __syncwarp(FULL);

    const int cc = lane & 3;
    const int ks = (lane >> 2) & 1;

    const uint2 q0 = s_c1[w][pt][ks];
    const uint2 q1 = s_c1[w][pt][2 + ks];
    const uint2 q2 = s_c1[w][pt][4 + ks];
    const __half2 A0 = *(__half2*)&q0.x, B0 = *(__half2*)&q0.y;
    const __half2 A1 = *(__half2*)&q1.x, B1 = *(__half2*)&q1.y;
    const __half2 A2 = *(__half2*)&q2.x, B2 = *(__half2*)&q2.y;

    const int row0 = gi0 & 511;
    const int col0 = gi1 & 511;
    const int p    = col0 & 1;                       // alignment parity
    const __half2* gsel = p ? g_xTb : g_xTa;
    const uint4* base = reinterpret_cast<const uint4*>(gsel)
        + ((size_t)(b_blk * HROWS + row0) * HSTRIDE + col0 + p + ks) * 4 + cc;

    const __half2 hz = __floats2half2_rn(0.f, 0.f);
    __half2 G1[4], G2[4];
#pragma unroll
    for (int c = 0; c < 4; c++) { G1[c] = hz; G2[c] = hz; }

#pragma unroll
    for (int j0 = 0; j0 < NJ; j0++) {
        const uint4* rp = base + j0 * ROW_U4;
        const uint4 d0 = __ldg(rp);
        const uint4 d1 = __ldg(rp + 8);    // +2 cells
        const uint4 d2 = __ldg(rp + 16);   // +4 cells
        const __half2* e0 = reinterpret_cast<const __half2*>(&d0);
        const __half2* e1 = reinterpret_cast<const __half2*>(&d1);
        const __half2* e2 = reinterpret_cast<const __half2*>(&d2);

        const uint2 c0p = s_c0[w][pt][j0];
        const __half2 C0R = *(const __half2*)&c0p.x;
        const __half2 C0I = *(const __half2*)&c0p.y;

#pragma unroll
        for (int c = 0; c < 4; c++) {
            __half2 r1 = __hmul2(A0, e0[c]);
            r1 = __hfma2(A1, e1[c], r1);
            r1 = __hfma2(A2, e2[c], r1);
            __half2 r2 = __hmul2(B0, e0[c]);
            r2 = __hfma2(B1, e1[c], r2);
            r2 = __hfma2(B2, e2[c], r2);
            const __half2 S = __hadd2(r1, __lowhigh2highlow(r2));
            G1[c] = __hfma2(C0R, S, G1[c]);
            G2[c] = __hfma2(C0I, S, G2[c]);
        }
    }

    // reduce the two cell slots (lane xor 4) in half2
#pragma unroll
    for (int c = 0; c < 4; c++) {
        unsigned u;
        u = __shfl_xor_sync(FULL, *(unsigned*)&G1[c], 4);
        G1[c] = __hadd2(G1[c], *(__half2*)&u);
        u = __shfl_xor_sync(FULL, *(unsigned*)&G2[c], 4);
        G2[c] = __hadd2(G2[c], *(__half2*)&u);
    }

    if (ks == 0) {
        const float2 ph = s_ph[w][pt];
        const int pp = w * 4 + pt;
#pragma unroll
        for (int c = 0; c < 4; c++) {
            const float2 g1 = __half22float2(G1[c]);
            const float2 g2 = __half22float2(G2[c]);
            const float ar = g1.x - g2.y;
            const float ai = g1.y + g2.x;
            const int coil = cc * 4 + c;
            s_out[coil * 2 + 0][pp] = ar * ph.x - ai * ph.y;
            s_out[coil * 2 + 1][pp] = ar * ph.y + ai * ph.x;
        }
    }
    __syncthreads();

    // out[b][coil][ri][m0+pp]: 32 rows x 32 consecutive m (128B runs)
#pragma unroll
    for (int i = tid; i < 32 * PPB; i += 256) {
        const int pp = i & (PPB - 1);
        const int r  = i >> 5;
        out[((size_t)(b_blk * NCOILS * 2) + r) * M_LEN + m0 + pp] = s_out[r][pp];
    }
}

extern "C" void kernel_launch(void* const* d_in, const int* in_sizes, int n_in,
                              void* d_out, int out_size) {
    const float* x  = (const float*)d_in[0];   // (2,16,2,512,512)
    const float* om = (const float*)d_in[1];   // (2,2,262144)
    const float* t0 = (const float*)d_in[2];   // (2,6145)
    const float* t1 = (const float*)d_in[3];   // (2,6145)
    float* out = (float*)d_out;                // (2,16,2,262144)

    int ncells_h = NBATCH * HROWS * HROWS;
    transpose_kernel<<<(ncells_h + 255) / 256, 256>>>(x);
    interp_kernel<<<(NBATCH * M_LEN) / PPB, 256>>>(om, t0, t1, out);
}